// round 17
// baseline (speedup 1.0000x reference)
#include <cuda_runtime.h>
#include <cstdint>

#define HID 128
#define T_STEPS 2048
#define BATCH 64
#define NOUT 5
#define MROWS (BATCH * T_STEPS)   // 131072

// -------------------- scratch (device globals; no allocation) --------------------
__device__ float g_xw[(size_t)MROWS * 384];   // input-projection buffer
__device__ float g_h0[(size_t)MROWS * HID];   // layer output ping
__device__ float g_h1[(size_t)MROWS * HID];   // layer output pong

// -------------------- packed f32x2 helpers --------------------
__device__ __forceinline__ unsigned long long pack2(float lo, float hi) {
    unsigned long long r;
    asm("mov.b64 %0, {%1, %2};" : "=l"(r) : "f"(lo), "f"(hi));
    return r;
}
__device__ __forceinline__ void unpack2(unsigned long long v, float& lo, float& hi) {
    asm("mov.b64 {%0, %1}, %2;" : "=f"(lo), "=f"(hi) : "l"(v));
}
#define FMA2(d, a, b, c) \
    asm("fma.rn.f32x2 %0, %1, %2, %3;" : "=l"(d) : "l"(a), "l"(b), "l"(c))

// ============================================================================
// GEMM (champion, verbatim): C = A[M,128] @ W[128,384] + bias (+brec<256)
// BM=128, BN=128, BK=128; grid=(M/128, 3), 256 thr, 133KB smem, 8x8 microtile.
// ============================================================================
__global__ __launch_bounds__(256, 1)
void gemm128(const float* __restrict__ A, const float* __restrict__ W,
             const float* __restrict__ bias, const float* __restrict__ brec,
             float* __restrict__ C, int M) {
    extern __shared__ float smem[];
    float* As = smem;              // As[k][m], pitch 132
    float* Bs = smem + 128 * 132;  // Bs[k][n], pitch 128

    const int m0 = blockIdx.x * 128;
    const int n0 = blockIdx.y * 128;
    const int tid = threadIdx.x;

    for (int idx = tid; idx < 128 * 32; idx += 256) {
        int r = idx >> 5, c4 = idx & 31;
        float4 v = *(const float4*)(A + (size_t)(m0 + r) * 128 + c4 * 4);
        As[(c4 * 4 + 0) * 132 + r] = v.x;
        As[(c4 * 4 + 1) * 132 + r] = v.y;
        As[(c4 * 4 + 2) * 132 + r] = v.z;
        As[(c4 * 4 + 3) * 132 + r] = v.w;
    }
    for (int idx = tid; idx < 128 * 32; idx += 256) {
        int k = idx >> 5, c4 = idx & 31;
        *(float4*)&Bs[k * 128 + c4 * 4] =
            *(const float4*)(W + (size_t)k * 384 + n0 + c4 * 4);
    }
    __syncthreads();

    const int tx = tid & 15, ty = tid >> 4;
    const int mr = ty * 8, nc = tx * 8;

    unsigned long long acc[8][4];
#pragma unroll
    for (int i = 0; i < 8; i++)
#pragma unroll
        for (int jj = 0; jj < 4; jj++) acc[i][jj] = 0ULL;

#pragma unroll 8
    for (int k = 0; k < 128; k++) {
        float4 a0 = *(const float4*)&As[k * 132 + mr];
        float4 a1 = *(const float4*)&As[k * 132 + mr + 4];
        ulonglong2 b0 = *(const ulonglong2*)&Bs[k * 128 + nc];
        ulonglong2 b1 = *(const ulonglong2*)&Bs[k * 128 + nc + 4];
        float av[8] = {a0.x, a0.y, a0.z, a0.w, a1.x, a1.y, a1.z, a1.w};
        unsigned long long bp[4] = {b0.x, b0.y, b1.x, b1.y};
#pragma unroll
        for (int i = 0; i < 8; i++) {
            unsigned long long ap = pack2(av[i], av[i]);
#pragma unroll
            for (int jj = 0; jj < 4; jj++) FMA2(acc[i][jj], ap, bp[jj], acc[i][jj]);
        }
    }

    float bv[8];
#pragma unroll
    for (int c = 0; c < 8; c++) {
        int n = n0 + nc + c;
        bv[c] = bias[n] + (n < 256 ? brec[n] : 0.0f);
    }

#pragma unroll
    for (int i = 0; i < 8; i++) {
        float o[8];
#pragma unroll
        for (int jj = 0; jj < 4; jj++) unpack2(acc[i][jj], o[2 * jj], o[2 * jj + 1]);
#pragma unroll
        for (int c = 0; c < 8; c++) o[c] += bv[c];
        float* cp = C + (size_t)(m0 + mr + i) * 384 + n0 + nc;
        *(float4*)cp = make_float4(o[0], o[1], o[2], o[3]);
        *(float4*)(cp + 4) = make_float4(o[4], o[5], o[6], o[7]);
    }
}

// ============================================================================
// GRU scan v8: TWO batches per CTA (weights are batch-invariant -> same 128
// weight regs serve both dots). 384 threads; thread j owns rk column j.
// Per step: both batches' dots (8 FMA chains), ONE shared barrier pair,
// combined tail on 256 threads (t<128: batch0, t<256: batch1).
// xw staged via double-buffered smem in 4-step blocks (R15 mechanism), one
// batch staged at s==2, the other at s==3.
// ============================================================================
__global__ __launch_bounds__(384, 1)
void scan_kernel(const float* __restrict__ xw, const float* __restrict__ rk,
                 const float* __restrict__ brec, float* __restrict__ hout) {
    const int bx = blockIdx.x;      // 0..31 (pair of batches)
    const int j = threadIdx.x;      // 0..383

    __shared__ __align__(16) float h_sh[2][HID];
    __shared__ float g_sh[2][384];
    extern __shared__ __align__(16) float xbuf[];   // [2 batch][2 buf][1536]
#define XB(bb, p, i) xbuf[((bb) * 2 + (p)) * 1536 + (i)]

    unsigned long long w2[64];
#pragma unroll
    for (int i = 0; i < 64; i++) {
        float a0 = rk[(size_t)(2 * i) * 384 + j];
        float a1 = rk[(size_t)(2 * i + 1) * 384 + j];
        w2[i] = pack2(a0, a1);
    }

    const float brh = brec[256 + (j & 127)];
    float h_reg = 0.0f;
    if (j < HID) { h_sh[0][j] = 0.0f; h_sh[1][j] = 0.0f; }

    const float4* xblk0 = (const float4*)(xw + (size_t)(2 * bx) * T_STEPS * 384);
    const float4* xblk1 = (const float4*)(xw + (size_t)(2 * bx + 1) * T_STEPS * 384);
    // preload: block0 -> buf0 (both batches); block1 -> regs
    float4 xr0 = xblk0[j];
    float4 xr1 = xblk1[j];
    *(float4*)&XB(0, 0, 4 * j) = xr0;
    *(float4*)&XB(1, 0, 4 * j) = xr1;
    xr0 = xblk0[384 + j];
    xr1 = xblk1[384 + j];

    float* hrow = hout + ((size_t)(2 * bx + (j >> 7)) * T_STEPS + 0) * HID + (j & 127);
    __syncthreads();

    for (int t = 0; t < T_STEPS; t++) {
        const int p = (t >> 2) & 1;
        const int s = t & 3;

        float xv0 = XB(0, p, s * 384 + j);
        float xv1 = XB(1, p, s * 384 + j);

        // both batches' dots with shared weights: 8 chains, 2 LDS.128/iter
        const ulonglong2* hp0 = (const ulonglong2*)h_sh[0];
        const ulonglong2* hp1 = (const ulonglong2*)h_sh[1];
        unsigned long long a0 = 0ULL, a1 = 0ULL, c0 = 0ULL, c1 = 0ULL;
#pragma unroll
        for (int i = 0; i < 32; i++) {
            ulonglong2 u = hp0[i];
            ulonglong2 x = hp1[i];
            FMA2(a0, u.x, w2[2 * i], a0);
            FMA2(a1, u.y, w2[2 * i + 1], a1);
            FMA2(c0, x.x, w2[2 * i], c0);
            FMA2(c1, x.y, w2[2 * i + 1], c1);
        }
        float l0, f0, l1, f1;
        unpack2(a0, l0, f0);
        unpack2(a1, l1, f1);
        float ri0 = (l0 + l1) + (f0 + f1);
        unpack2(c0, l0, f0);
        unpack2(c1, l1, f1);
        float ri1 = (l0 + l1) + (f0 + f1);

        g_sh[0][j] = (j < 256) ? (ri0 + xv0) : ri0;
        g_sh[1][j] = (j < 256) ? (ri1 + xv1) : ri1;
        __syncthreads();

        // stage next xw block (regs hold block blk+1; LDG block blk+2)
        if (s == 2) {
            *(float4*)&XB(0, p ^ 1, 4 * j) = xr0;
            int blk2 = (t >> 2) + 2;
            if (blk2 > 511) blk2 = 511;
            xr0 = xblk0[(size_t)blk2 * 384 + j];
        } else if (s == 3) {
            *(float4*)&XB(1, p ^ 1, 4 * j) = xr1;
            int blk2 = (t >> 2) + 2;
            if (blk2 > 511) blk2 = 511;
            xr1 = xblk1[(size_t)blk2 * 384 + j];
        }

        if (j < 256) {
            const int bb = j >> 7;
            const int m = j & 127;
            float gz = g_sh[bb][m];
            float gr = g_sh[bb][128 + m];
            float ph = g_sh[bb][256 + m] + brh;
            float xh = XB(bb, p, s * 384 + 256 + m);
            float z = __fdividef(1.0f, 1.0f + __expf(-gz));
            float r = __fdividef(1.0f, 1.0f + __expf(-gr));
            float e2 = __expf(-2.0f * (xh + r * ph));
            float hh = __fdividef(2.0f, 1.0f + e2) - 1.0f;   // tanh
            float hn = z * h_reg + (1.0f - z) * hh;
            h_reg = hn;
            h_sh[bb][m] = hn;
            hrow[(size_t)t * HID] = hn;
        }
        __syncthreads();
    }
#undef XB
}

// ============================================================================
// Output head: out[M,5] = H[M,128] @ wo[128,5] + bo
// ============================================================================
__global__ __launch_bounds__(256, 1)
void outproj(const float* __restrict__ H, const float* __restrict__ wo,
             const float* __restrict__ bo, float* __restrict__ out, int M) {
    __shared__ float ws[HID * NOUT];
    __shared__ float bs[NOUT];
    for (int i = threadIdx.x; i < HID * NOUT; i += blockDim.x) ws[i] = wo[i];
    if (threadIdx.x < NOUT) bs[threadIdx.x] = bo[threadIdx.x];
    __syncthreads();

    int r = blockIdx.x * blockDim.x + threadIdx.x;
    if (r >= M) return;

    const float4* hr = (const float4*)(H + (size_t)r * HID);
    float acc[NOUT];
#pragma unroll
    for (int o = 0; o < NOUT; o++) acc[o] = bs[o];

#pragma unroll
    for (int k4 = 0; k4 < 32; k4++) {
        float4 v = hr[k4];
#pragma unroll
        for (int o = 0; o < NOUT; o++) {
            acc[o] += v.x * ws[(k4 * 4 + 0) * NOUT + o];
            acc[o] += v.y * ws[(k4 * 4 + 1) * NOUT + o];
            acc[o] += v.z * ws[(k4 * 4 + 2) * NOUT + o];
            acc[o] += v.w * ws[(k4 * 4 + 3) * NOUT + o];
        }
    }
#pragma unroll
    for (int o = 0; o < NOUT; o++) out[(size_t)r * NOUT + o] = acc[o];
}

// ============================================================================
// Launcher: single stream, sequential (allocation-free).
// ============================================================================
extern "C" void kernel_launch(void* const* d_in, const int* in_sizes, int n_in,
                              void* d_out, int out_size) {
    const float* x   = (const float*)d_in[0];
    const float* k0  = (const float*)d_in[1];
    const float* rk0 = (const float*)d_in[2];
    const float* b0  = (const float*)d_in[3];
    const float* k1  = (const float*)d_in[4];
    const float* rk1 = (const float*)d_in[5];
    const float* b1  = (const float*)d_in[6];
    const float* k2  = (const float*)d_in[7];
    const float* rk2 = (const float*)d_in[8];
    const float* b2  = (const float*)d_in[9];
    const float* wo  = (const float*)d_in[10];
    const float* bo  = (const float*)d_in[11];
    float* out = (float*)d_out;

    float *xwp, *h0p, *h1p;
    cudaGetSymbolAddress((void**)&xwp, g_xw);
    cudaGetSymbolAddress((void**)&h0p, g_h0);
    cudaGetSymbolAddress((void**)&h1p, g_h1);

    const int M = MROWS;
    const size_t smem = (128 * 132 + 128 * 128) * sizeof(float);  // 133 KB
    cudaFuncSetAttribute(gemm128, cudaFuncAttributeMaxDynamicSharedMemorySize,
                         (int)smem);

    const int scan_smem = 2 * 2 * 1536 * (int)sizeof(float);  // 24 KB dynamic

    dim3 ggrid(M / 128, 3);

    // Layer 0
    gemm128<<<ggrid, 256, smem>>>(x, k0, b0, b0 + 384, xwp, M);
    scan_kernel<<<BATCH / 2, 384, scan_smem>>>(xwp, rk0, b0 + 384, h0p);
    // Layer 1
    gemm128<<<ggrid, 256, smem>>>(h0p, k1, b1, b1 + 384, xwp, M);
    scan_kernel<<<BATCH / 2, 384, scan_smem>>>(xwp, rk1, b1 + 384, h1p);
    // Layer 2
    gemm128<<<ggrid, 256, smem>>>(h1p, k2, b2, b2 + 384, xwp, M);
    scan_kernel<<<BATCH / 2, 384, scan_smem>>>(xwp, rk2, b2 + 384, h0p);
    // Output head
    outproj<<<(MROWS + 255) / 256, 256>>>(h0p, wo, bo, out, MROWS);
}